// round 12
// baseline (speedup 1.0000x reference)
#include <cuda_runtime.h>
#include <cuda_bf16.h>
#include <stdint.h>
#include <math.h>

#define DMODEL 1024
#define NH     16
#define DKH    64
#define BATCH  2
#define SEQ    2048
#define MROWS  (BATCH*SEQ)        // 4096

// ---------------------------------------------------------------------------
// Scratch (device globals; referenced ONLY inside device code — never passed
// as kernel args: host symbol decay + GB300 ATS silently redirects to host)
// ---------------------------------------------------------------------------
__device__ __nv_bfloat16 g_Ahi[MROWS * DMODEL];        // activations hi
__device__ __nv_bfloat16 g_Alo[MROWS * DMODEL];        // activations lo
__device__ __nv_bfloat16 g_Bhi[3 * DMODEL * DMODEL];   // WqkvT hi [3072][1024]
__device__ __nv_bfloat16 g_Blo[3 * DMODEL * DMODEL];
__device__ __nv_bfloat16 g_Chi[DMODEL * DMODEL];       // WoutT hi [1024][1024]
__device__ __nv_bfloat16 g_Clo[DMODEL * DMODEL];
#define BHSD (BATCH * NH * SEQ * DKH)
__device__ __nv_bfloat16 g_Qhi[BHSD], g_Qlo[BHSD];     // [bh][s][d], pre-scaled x0.125
__device__ __nv_bfloat16 g_Khi[BHSD], g_Klo[BHSD];     // [bh][s][d]
__device__ __nv_bfloat16 g_Vthi[BHSD], g_Vtlo[BHSD];   // [bh][d][s]

// ---------------------------------------------------------------------------
__device__ __forceinline__ uint32_t smem_u32(const void* p) {
    uint32_t a;
    asm("{ .reg .u64 t; cvta.to.shared.u64 t, %1; cvt.u32.u64 %0, t; }" : "=r"(a) : "l"(p));
    return a;
}
__device__ __forceinline__ void mma_bf16(float* c, const uint32_t* a, const uint32_t* b) {
    asm volatile("mma.sync.aligned.m16n8k16.row.col.f32.bf16.bf16.f32 "
                 "{%0,%1,%2,%3}, {%4,%5,%6,%7}, {%8,%9}, {%0,%1,%2,%3};"
                 : "+f"(c[0]), "+f"(c[1]), "+f"(c[2]), "+f"(c[3])
                 : "r"(a[0]), "r"(a[1]), "r"(a[2]), "r"(a[3]), "r"(b[0]), "r"(b[1]));
}
__device__ __forceinline__ void ldsm4(uint32_t* r, uint32_t a) {
    asm volatile("ldmatrix.sync.aligned.m8n8.x4.shared.b16 {%0,%1,%2,%3}, [%4];"
                 : "=r"(r[0]), "=r"(r[1]), "=r"(r[2]), "=r"(r[3]) : "r"(a));
}
__device__ __forceinline__ void cpa16(uint32_t s, const void* g) {
    asm volatile("cp.async.ca.shared.global [%0], [%1], 16;" :: "r"(s), "l"(g));
}
#define CP_COMMIT() asm volatile("cp.async.commit_group;" ::: "memory")
#define CP_WAIT1()  asm volatile("cp.async.wait_group 1;" ::: "memory")

// ---------------------------------------------------------------------------
// Fused prep: x-split | Wqkv trans-split | Wout trans-split by block range
// ---------------------------------------------------------------------------
#define SPLIT_BLKS 4096
#define WQKV_BLKS  3072
#define WOUT_BLKS  1024
#define PREP_BLKS  (SPLIT_BLKS + WQKV_BLKS + WOUT_BLKS)

__global__ __launch_bounds__(256)
void prep_kernel(const float* __restrict__ x,
                 const float* __restrict__ Wqkv,
                 const float* __restrict__ Wout)
{
    int bid = blockIdx.x;
    int tid = threadIdx.x;

    if (bid < SPLIT_BLKS) {
        int i = bid * 256 + tid;
        float4 v = ((const float4*)x)[i];
        __nv_bfloat16 h0 = __float2bfloat16(v.x); __nv_bfloat16 l0 = __float2bfloat16(v.x - __bfloat162float(h0));
        __nv_bfloat16 h1 = __float2bfloat16(v.y); __nv_bfloat16 l1 = __float2bfloat16(v.y - __bfloat162float(h1));
        __nv_bfloat16 h2 = __float2bfloat16(v.z); __nv_bfloat16 l2 = __float2bfloat16(v.z - __bfloat162float(h2));
        __nv_bfloat16 h3 = __float2bfloat16(v.w); __nv_bfloat16 l3 = __float2bfloat16(v.w - __bfloat162float(h3));
        ((__nv_bfloat162*)g_Ahi)[i*2+0] = __nv_bfloat162(h0, h1);
        ((__nv_bfloat162*)g_Ahi)[i*2+1] = __nv_bfloat162(h2, h3);
        ((__nv_bfloat162*)g_Alo)[i*2+0] = __nv_bfloat162(l0, l1);
        ((__nv_bfloat162*)g_Alo)[i*2+1] = __nv_bfloat162(l2, l3);
        return;
    }

    __shared__ float t[32][33];
    const float* W;
    __nv_bfloat16 *Thi, *Tlo;
    int n0, k0, Ndim;
    if (bid < SPLIT_BLKS + WQKV_BLKS) {
        int tb = bid - SPLIT_BLKS;
        W = Wqkv; Thi = g_Bhi; Tlo = g_Blo; Ndim = 3 * DMODEL;
        n0 = (tb % 96) * 32; k0 = (tb / 96) * 32;
    } else {
        int tb = bid - SPLIT_BLKS - WQKV_BLKS;
        W = Wout; Thi = g_Chi; Tlo = g_Clo; Ndim = DMODEL;
        n0 = (tb % 32) * 32; k0 = (tb / 32) * 32;
    }
    int xx = tid & 31, yy = tid >> 5;
    #pragma unroll
    for (int r = 0; r < 4; r++)
        t[yy + r * 8][xx] = W[(size_t)(k0 + yy + r * 8) * Ndim + n0 + xx];
    __syncthreads();
    #pragma unroll
    for (int r = 0; r < 4; r++) {
        int n = n0 + yy + r * 8;
        int k = k0 + xx;
        float v = t[xx][yy + r * 8];
        __nv_bfloat16 h = __float2bfloat16(v);
        __nv_bfloat16 l = __float2bfloat16(v - __bfloat162float(h));
        Thi[(size_t)n * DMODEL + k] = h;
        Tlo[(size_t)n * DMODEL + k] = l;
    }
}

// ---------------------------------------------------------------------------
// HMMA GEMM v2: 512 threads, CTA tile 256x128, BK=32, 3-stage cp.async,
// wait_group 1 + single sync/iter. 16 warps (4x4), warp tile 64x32.
// MODE 0: QKV proj -> bf16 Q(scaled)/K [s][d], V^T [d][s]. MODE 1: out proj.
// ---------------------------------------------------------------------------
#define ROWB    80
#define A_MAT   (256 * ROWB)         // 20480
#define B_MAT   (128 * ROWB)         // 10240
#define STAGE_B (2 * A_MAT + 2 * B_MAT)  // 61440
#define GEMM_SMEM (3 * STAGE_B)          // 184320
// stage layout: [Ah 20480][Al 20480][Bh 10240][Bl 10240]
#define OFF_AL  A_MAT
#define OFF_BH  (2 * A_MAT)
#define OFF_BL  (2 * A_MAT + B_MAT)

template<int MODE>
__global__ __launch_bounds__(512, 1)
void gemm_mma(const float* __restrict__ bias, float* __restrict__ C)
{
    extern __shared__ char smem[];
    const uint32_t sbase = smem_u32(smem);
    const int tid = threadIdx.x, wid = tid >> 5, lane = tid & 31;
    const int m0 = blockIdx.y * 256, n0 = blockIdx.x * 128;
    const int warpM = wid >> 2, warpN = wid & 3;     // 4 x 4
    const int gid = lane >> 2, tg = lane & 3;

    const __nv_bfloat16* Bhi = (MODE == 0) ? g_Bhi : g_Chi;
    const __nv_bfloat16* Blo = (MODE == 0) ? g_Blo : g_Clo;

    // loads: A rows tid>>1 (0..255), chunks 2*(tid&1)+{0,1}; B rows tid>>2, chunk tid&3
    const int ar = tid >> 1, ac = (tid & 1) * 2;     // A chunk pair
    const int br = tid >> 2, bc = tid & 3;
    const __nv_bfloat16* pAh = g_Ahi + (size_t)(m0 + ar) * 1024 + ac * 8;
    const __nv_bfloat16* pAl = g_Alo + (size_t)(m0 + ar) * 1024 + ac * 8;
    const __nv_bfloat16* pBh = Bhi   + (size_t)(n0 + br) * 1024 + bc * 8;
    const __nv_bfloat16* pBl = Blo   + (size_t)(n0 + br) * 1024 + bc * 8;
    const uint32_t sa = (uint32_t)(ar * ROWB + ac * 16);
    const uint32_t sb_ = (uint32_t)(br * ROWB + bc * 16);

    float acc[4][4][4];
    #pragma unroll
    for (int a = 0; a < 4; a++)
        #pragma unroll
        for (int b = 0; b < 4; b++)
            #pragma unroll
            for (int d = 0; d < 4; d++) acc[a][b][d] = 0.f;

    #define GISSUE(c) do {                                                    \
        size_t go = (size_t)(c) * 32;                                         \
        uint32_t sp = sbase + ((c) % 3) * STAGE_B;                            \
        cpa16(sp + sa,               pAh + go);                               \
        cpa16(sp + sa + 16,          pAh + go + 8);                           \
        cpa16(sp + OFF_AL + sa,      pAl + go);                               \
        cpa16(sp + OFF_AL + sa + 16, pAl + go + 8);                           \
        cpa16(sp + OFF_BH + sb_,     pBh + go);                               \
        cpa16(sp + OFF_BL + sb_,     pBl + go);                               \
        CP_COMMIT();                                                          \
    } while (0)

    // ldmatrix lane addressing
    const uint32_t a_lm = (uint32_t)((warpM * 64 + (lane & 15)) * ROWB + (lane >> 4) * 16);
    const uint32_t b_lm = (uint32_t)((warpN * 32 + (lane & 7)) * ROWB
                        + ((lane >> 3) & 1) * 16) + OFF_BH + (lane >= 16 ? B_MAT : 0);

    GISSUE(0);
    GISSUE(1);

    for (int c = 0; c < 32; c++) {
        CP_WAIT1();                    // stage c landed (c+1 may be in flight)
        __syncthreads();               // visible everywhere; reads of c-1 done
        if (c + 2 < 32) GISSUE(c + 2); // into buf (c+2)%3 = (c-1)%3 — safe

        const uint32_t sp = sbase + (c % 3) * STAGE_B;
        #pragma unroll
        for (int ks = 0; ks < 2; ks++) {
            const uint32_t kb = ks * 32;
            uint32_t bb[4][4];
            #pragma unroll
            for (int nt = 0; nt < 4; nt++)
                ldsm4(bb[nt], sp + b_lm + nt * (8 * ROWB) + kb);
            #pragma unroll
            for (int mt = 0; mt < 4; mt++) {
                uint32_t ah[4], al_[4];
                ldsm4(ah,  sp + a_lm + mt * (16 * ROWB) + kb);
                ldsm4(al_, sp + OFF_AL + a_lm + mt * (16 * ROWB) + kb);
                #pragma unroll
                for (int nt = 0; nt < 4; nt++) {
                    mma_bf16(acc[mt][nt], ah,  bb[nt]);
                    mma_bf16(acc[mt][nt], ah,  bb[nt] + 2);
                    mma_bf16(acc[mt][nt], al_, bb[nt]);
                }
            }
        }
    }

    #pragma unroll
    for (int mt = 0; mt < 4; mt++) {
        #pragma unroll
        for (int nt = 0; nt < 4; nt++) {
            int col = n0 + warpN * 32 + nt * 8 + tg * 2;
            float2 bv = *(const float2*)(bias + col);
            #pragma unroll
            for (int h = 0; h < 2; h++) {
                int row = m0 + warpM * 64 + mt * 16 + gid + h * 8;
                float vx = acc[mt][nt][h * 2 + 0] + bv.x;
                float vy = acc[mt][nt][h * 2 + 1] + bv.y;
                if (MODE == 0) {
                    int which = col >> 10;
                    int rem   = col & 1023;
                    int hh    = rem >> 6;
                    int d     = rem & 63;
                    int bb2   = row >> 11;
                    int s     = row & 2047;
                    size_t hb = (size_t)(bb2 * NH + hh) * (SEQ * DKH);
                    if (which == 2) {
                        __nv_bfloat16 hx = __float2bfloat16(vx);
                        __nv_bfloat16 hy = __float2bfloat16(vy);
                        __nv_bfloat16 lx = __float2bfloat16(vx - __bfloat162float(hx));
                        __nv_bfloat16 ly = __float2bfloat16(vy - __bfloat162float(hy));
                        size_t voff = hb + (size_t)d * SEQ + s;
                        g_Vthi[voff]       = hx;
                        g_Vthi[voff + SEQ] = hy;
                        g_Vtlo[voff]       = lx;
                        g_Vtlo[voff + SEQ] = ly;
                    } else {
                        size_t off = hb + (size_t)s * DKH + d;
                        __nv_bfloat16 *ph, *pl;
                        if (which == 0) { vx *= 0.125f; vy *= 0.125f; ph = g_Qhi; pl = g_Qlo; }
                        else            { ph = g_Khi; pl = g_Klo; }
                        __nv_bfloat162 h2 = __float22bfloat162_rn(make_float2(vx, vy));
                        __nv_bfloat162 l2 = __float22bfloat162_rn(make_float2(
                            vx - __bfloat162float(h2.x), vy - __bfloat162float(h2.y)));
                        *(__nv_bfloat162*)(ph + off) = h2;
                        *(__nv_bfloat162*)(pl + off) = l2;
                    }
                } else {
                    *(float2*)&C[(size_t)row * DMODEL + col] = make_float2(vx, vy);
                }
            }
        }
    }
    #undef GISSUE
}

// ---------------------------------------------------------------------------
// HMMA flash attention: 3-stage cp.async, ONE sync per tile (unchanged).
// ---------------------------------------------------------------------------
#define KROWB   144
#define AMAT_B  (64 * KROWB)
#define ATILE_B (4 * AMAT_B)
#define ATTN_SMEM3 (3 * ATILE_B)

__global__ __launch_bounds__(256, 2)
void attn_mma()
{
    extern __shared__ char asmem[];
    const uint32_t sbase = smem_u32(asmem);

    const int tid = threadIdx.x, wid = tid >> 5, lane = tid & 31;
    const int gid = lane >> 2, tg = lane & 3;
    const int bh = blockIdx.y;
    const int q0 = blockIdx.x * 128;

    const size_t bo = (size_t)bh * (SEQ * DKH);
    const __nv_bfloat16* Qh = g_Qhi + bo;
    const __nv_bfloat16* Ql = g_Qlo + bo;
    const __nv_bfloat16* Kh = g_Khi + bo;
    const __nv_bfloat16* Kl = g_Klo + bo;
    const __nv_bfloat16* Vh = g_Vthi + bo;
    const __nv_bfloat16* Vl = g_Vtlo + bo;

    uint32_t qh[4][4], ql[4][4];
    {
        int r = q0 + wid * 16 + gid;
        #pragma unroll
        for (int ks = 0; ks < 4; ks++) {
            size_t e = (size_t)r * DKH + ks * 16 + tg * 2;
            qh[ks][0] = *(const uint32_t*)(Qh + e);
            qh[ks][1] = *(const uint32_t*)(Qh + e + 8 * DKH);
            qh[ks][2] = *(const uint32_t*)(Qh + e + 8);
            qh[ks][3] = *(const uint32_t*)(Qh + e + 8 * DKH + 8);
            ql[ks][0] = *(const uint32_t*)(Ql + e);
            ql[ks][1] = *(const uint32_t*)(Ql + e + 8 * DKH);
            ql[ks][2] = *(const uint32_t*)(Ql + e + 8);
            ql[ks][3] = *(const uint32_t*)(Ql + e + 8 * DKH + 8);
        }
    }

    float o[8][4];
    #pragma unroll
    for (int i = 0; i < 8; i++)
        #pragma unroll
        for (int j = 0; j < 4; j++) o[i][j] = 0.f;
    float m0v = -1e30f, m1v = -1e30f, l0 = 0.f, l1 = 0.f;

    const int lr0 = tid >> 3;
    const int lc  = tid & 7;
    const uint32_t lmrow = (uint32_t)((lane & 7) * KROWB + ((lane >> 3) & 1) * 16)
                         + (lane >= 16 ? AMAT_B : 0);

    #define AISSUE(t) do {                                                    \
        size_t gk = (size_t)((t) * 64 + lr0) * DKH + lc * 8;                  \
        size_t gv = (size_t)lr0 * SEQ + (t) * 64 + lc * 8;                    \
        uint32_t sk = sbase + ((t) % 3) * ATILE_B + lr0 * KROWB + lc * 16;    \
        cpa16(sk,                           Kh + gk);                         \
        cpa16(sk + 32 * KROWB,              Kh + gk + 32 * DKH);              \
        cpa16(sk + AMAT_B,                  Kl + gk);                         \
        cpa16(sk + AMAT_B + 32 * KROWB,     Kl + gk + 32 * DKH);              \
        cpa16(sk + 2 * AMAT_B,              Vh + gv);                         \
        cpa16(sk + 2 * AMAT_B + 32 * KROWB, Vh + gv + 32 * SEQ);              \
        cpa16(sk + 3 * AMAT_B,              Vl + gv);                         \
        cpa16(sk + 3 * AMAT_B + 32 * KROWB, Vl + gv + 32 * SEQ);              \
        CP_COMMIT();                                                          \
    } while (0)

    AISSUE(0);
    AISSUE(1);

    for (int t = 0; t < 32; t++) {
        CP_WAIT1();
        __syncthreads();
        if (t + 2 < 32) AISSUE(t + 2);

        const uint32_t sb = sbase + (t % 3) * ATILE_B;

        float sc[8][4];
        #pragma unroll
        for (int nt = 0; nt < 8; nt++)
            #pragma unroll
            for (int j = 0; j < 4; j++) sc[nt][j] = 0.f;

        #pragma unroll
        for (int ks = 0; ks < 4; ks++) {
            #pragma unroll
            for (int nt = 0; nt < 8; nt++) {
                uint32_t kb[4];
                ldsm4(kb, sb + nt * (8 * KROWB) + ks * 32 + lmrow);
                mma_bf16(sc[nt], qh[ks], kb);
                mma_bf16(sc[nt], qh[ks], kb + 2);
                mma_bf16(sc[nt], ql[ks], kb);
            }
        }

        float mx0 = -1e30f, mx1 = -1e30f;
        #pragma unroll
        for (int nt = 0; nt < 8; nt++) {
            mx0 = fmaxf(mx0, fmaxf(sc[nt][0], sc[nt][1]));
            mx1 = fmaxf(mx1, fmaxf(sc[nt][2], sc[nt][3]));
        }
        mx0 = fmaxf(mx0, __shfl_xor_sync(0xffffffffu, mx0, 1));
        mx0 = fmaxf(mx0, __shfl_xor_sync(0xffffffffu, mx0, 2));
        mx1 = fmaxf(mx1, __shfl_xor_sync(0xffffffffu, mx1, 1));
        mx1 = fmaxf(mx1, __shfl_xor_sync(0xffffffffu, mx1, 2));
        float nm0 = fmaxf(m0v, mx0), nm1 = fmaxf(m1v, mx1);
        float a0 = __expf(m0v - nm0), a1 = __expf(m1v - nm1);
        m0v = nm0; m1v = nm1;

        float rs0 = 0.f, rs1 = 0.f;
        #pragma unroll
        for (int nt = 0; nt < 8; nt++) {
            sc[nt][0] = __expf(sc[nt][0] - nm0);
            sc[nt][1] = __expf(sc[nt][1] - nm0);
            sc[nt][2] = __expf(sc[nt][2] - nm1);
            sc[nt][3] = __expf(sc[nt][3] - nm1);
            rs0 += sc[nt][0] + sc[nt][1];
            rs1 += sc[nt][2] + sc[nt][3];
        }
        rs0 += __shfl_xor_sync(0xffffffffu, rs0, 1);
        rs0 += __shfl_xor_sync(0xffffffffu, rs0, 2);
        rs1 += __shfl_xor_sync(0xffffffffu, rs1, 1);
        rs1 += __shfl_xor_sync(0xffffffffu, rs1, 2);
        l0 = l0 * a0 + rs0;
        l1 = l1 * a1 + rs1;
        #pragma unroll
        for (int nt = 0; nt < 8; nt++) {
            o[nt][0] *= a0; o[nt][1] *= a0;
            o[nt][2] *= a1; o[nt][3] *= a1;
        }

        #pragma unroll
        for (int kt = 0; kt < 4; kt++) {
            uint32_t pah[4], pal[4];
            #pragma unroll
            for (int half = 0; half < 2; half++) {
                const float* s4 = sc[2 * kt + half];
                __nv_bfloat162 h01 = __float22bfloat162_rn(make_float2(s4[0], s4[1]));
                __nv_bfloat162 h23 = __float22bfloat162_rn(make_float2(s4[2], s4[3]));
                __nv_bfloat162 l01 = __float22bfloat162_rn(make_float2(
                    s4[0] - __bfloat162float(h01.x), s4[1] - __bfloat162float(h01.y)));
                __nv_bfloat162 l23 = __float22bfloat162_rn(make_float2(
                    s4[2] - __bfloat162float(h23.x), s4[3] - __bfloat162float(h23.y)));
                pah[2 * half + 0] = *(uint32_t*)&h01;
                pah[2 * half + 1] = *(uint32_t*)&h23;
                pal[2 * half + 0] = *(uint32_t*)&l01;
                pal[2 * half + 1] = *(uint32_t*)&l23;
            }
            #pragma unroll
            for (int nt2 = 0; nt2 < 8; nt2++) {
                uint32_t vb[4];
                ldsm4(vb, sb + 2 * AMAT_B + nt2 * (8 * KROWB) + kt * 32 + lmrow);
                mma_bf16(o[nt2], pah, vb);
                mma_bf16(o[nt2], pah, vb + 2);
                mma_bf16(o[nt2], pal, vb);
            }
        }
    }
    #undef AISSUE

    int b = bh >> 4, h = bh & 15;
    float i0 = 1.f / l0, i1 = 1.f / l1;
    int r = q0 + wid * 16 + gid;
    #pragma unroll
    for (int nt2 = 0; nt2 < 8; nt2++) {
        int d = h * DKH + nt2 * 8 + tg * 2;
        size_t off0 = (size_t)(b * SEQ + r) * DMODEL + d;
        size_t off1 = (size_t)(b * SEQ + r + 8) * DMODEL + d;
        float v0x = o[nt2][0] * i0, v0y = o[nt2][1] * i0;
        float v1x = o[nt2][2] * i1, v1y = o[nt2][3] * i1;
        __nv_bfloat162 h0 = __float22bfloat162_rn(make_float2(v0x, v0y));
        __nv_bfloat162 l0v = __float22bfloat162_rn(make_float2(
            v0x - __bfloat162float(h0.x), v0y - __bfloat162float(h0.y)));
        __nv_bfloat162 h1 = __float22bfloat162_rn(make_float2(v1x, v1y));
        __nv_bfloat162 l1v = __float22bfloat162_rn(make_float2(
            v1x - __bfloat162float(h1.x), v1y - __bfloat162float(h1.y)));
        *(__nv_bfloat162*)(g_Ahi + off0) = h0;
        *(__nv_bfloat162*)(g_Alo + off0) = l0v;
        *(__nv_bfloat162*)(g_Ahi + off1) = h1;
        *(__nv_bfloat162*)(g_Alo + off1) = l1v;
    }
}

// ---------------------------------------------------------------------------
extern "C" void kernel_launch(void* const* d_in, const int* in_sizes, int n_in,
                              void* d_out, int out_size)
{
    const float* x     = (const float*)d_in[0];
    const float* Wqkv  = (const float*)d_in[1];
    const float* bqkv  = (const float*)d_in[2];
    const float* Wout  = (const float*)d_in[3];
    const float* bout  = (const float*)d_in[4];
    float* out = (float*)d_out;

    cudaFuncSetAttribute(gemm_mma<0>, cudaFuncAttributeMaxDynamicSharedMemorySize, GEMM_SMEM);
    cudaFuncSetAttribute(gemm_mma<1>, cudaFuncAttributeMaxDynamicSharedMemorySize, GEMM_SMEM);
    cudaFuncSetAttribute(attn_mma, cudaFuncAttributeMaxDynamicSharedMemorySize, ATTN_SMEM3);

    // 1) fused prep
    prep_kernel<<<PREP_BLKS, 256>>>(x, Wqkv, Wout);
    // 2) QKV GEMM (tile 256x128, 512 thr) -> Q/K [s][d], V^T [d][s]
    gemm_mma<0><<<dim3(3 * DMODEL / 128, MROWS / 256), 512, GEMM_SMEM>>>(bqkv, nullptr);
    // 3) HMMA flash attention -> g_Ahi/g_Alo
    attn_mma<<<dim3(SEQ / 128, BATCH * NH), 256, ATTN_SMEM3>>>();
    // 4) output projection (tile 256x128)
    gemm_mma<1><<<dim3(DMODEL / 128, MROWS / 256), 512, GEMM_SMEM>>>(bout, out);
}